// round 1
// baseline (speedup 1.0000x reference)
#include <cuda_runtime.h>

#define NN 100000
#define NE 1000000
#define D  64

// ---- device scratch (static, no allocation) ----
__device__ int   g_deg[NN];
__device__ float g_dinv[NN];
__device__ int   g_off[NN + 1];
__device__ int   g_pos[NN];
__device__ int   g_csr_src[NE];
__device__ float g_h1[NN * D];
__device__ float g_h2[NN * D];

// 1) deg[i] = 1 (self loop)
__global__ void k_init_deg() {
    int i = blockIdx.x * blockDim.x + threadIdx.x;
    if (i < NN) g_deg[i] = 1;
}

// 2) histogram of in-degree over dst
__global__ void k_hist(const int* __restrict__ dst) {
    int e = blockIdx.x * blockDim.x + threadIdx.x;
    if (e < NE) atomicAdd(&g_deg[dst[e]], 1);
}

// 3) dinv = rsqrt(deg)  (deg >= 1 always due to self loop)
__global__ void k_dinv() {
    int i = blockIdx.x * blockDim.x + threadIdx.x;
    if (i < NN) g_dinv[i] = rsqrtf((float)g_deg[i]);
}

// 4) exclusive prefix sum of (deg-1) -> g_off, also seed g_pos
__global__ void k_scan() {
    __shared__ int s[1024];
    __shared__ int carry;
    if (threadIdx.x == 0) carry = 0;
    __syncthreads();
    for (int base = 0; base < NN; base += 1024) {
        int i = base + threadIdx.x;
        int v = (i < NN) ? (g_deg[i] - 1) : 0;
        s[threadIdx.x] = v;
        __syncthreads();
        // Hillis–Steele inclusive scan
        for (int d = 1; d < 1024; d <<= 1) {
            int t = (threadIdx.x >= d) ? s[threadIdx.x - d] : 0;
            __syncthreads();
            s[threadIdx.x] += t;
            __syncthreads();
        }
        if (i < NN) {
            int ex = carry + s[threadIdx.x] - v;  // exclusive
            g_off[i] = ex;
            g_pos[i] = ex;
        }
        __syncthreads();
        if (threadIdx.x == 0) carry += s[1023];
        __syncthreads();
    }
    if (threadIdx.x == 0) g_off[NN] = carry;  // == NE
}

// 5) scatter edge sources into CSR buckets by dst
__global__ void k_scatter(const int* __restrict__ src, const int* __restrict__ dst) {
    int e = blockIdx.x * blockDim.x + threadIdx.x;
    if (e < NE) {
        int d = dst[e];
        int p = atomicAdd(&g_pos[d], 1);
        g_csr_src[p] = src[e];
    }
}

// 6) hop 1: g_h1 = A_hat * x   (warp per node, float2 per lane)
__global__ void k_hop1(const float* __restrict__ x) {
    int gw   = (blockIdx.x * blockDim.x + threadIdx.x) >> 5;
    int lane = threadIdx.x & 31;
    if (gw >= NN) return;
    const int i = gw;
    float di = g_dinv[i];
    const float2* in2 = (const float2*)x;
    float2 a = __ldg(&in2[i * 32 + lane]);
    float2 acc;
    acc.x = di * di * a.x;
    acc.y = di * di * a.y;
    int beg = g_off[i], end = g_off[i + 1];
    for (int j = beg; j < end; j++) {
        int   s = __ldg(&g_csr_src[j]);
        float w = __ldg(&g_dinv[s]) * di;
        float2 v = __ldg(&in2[s * 32 + lane]);
        acc.x += w * v.x;
        acc.y += w * v.y;
    }
    ((float2*)g_h1)[i * 32 + lane] = acc;
}

// 7) hop 2: g_h2 = A_hat * g_h1
__global__ void k_hop2() {
    int gw   = (blockIdx.x * blockDim.x + threadIdx.x) >> 5;
    int lane = threadIdx.x & 31;
    if (gw >= NN) return;
    const int i = gw;
    float di = g_dinv[i];
    const float2* in2 = (const float2*)g_h1;
    float2 a = __ldg(&in2[i * 32 + lane]);
    float2 acc;
    acc.x = di * di * a.x;
    acc.y = di * di * a.y;
    int beg = g_off[i], end = g_off[i + 1];
    for (int j = beg; j < end; j++) {
        int   s = __ldg(&g_csr_src[j]);
        float w = __ldg(&g_dinv[s]) * di;
        float2 v = __ldg(&in2[s * 32 + lane]);
        acc.x += w * v.x;
        acc.y += w * v.y;
    }
    ((float2*)g_h2)[i * 32 + lane] = acc;
}

// 8) out = g_h2 @ W^T + b
__global__ void k_lin(const float* __restrict__ W, const float* __restrict__ b,
                      float* __restrict__ out) {
    __shared__ float Wt[D * D];   // Wt[k*D + c] = W[c*D + k]
    __shared__ float bs[D];
    __shared__ float hs[4][D];
    for (int t = threadIdx.x; t < D * D; t += blockDim.x) {
        int c = t / D, k = t % D;
        Wt[k * D + c] = W[c * D + k];
    }
    if (threadIdx.x < D) bs[threadIdx.x] = b[threadIdx.x];
    __syncthreads();

    int rl = threadIdx.x / D;   // 0..3 (local row)
    int c  = threadIdx.x % D;   // output column

    for (int r0 = blockIdx.x * 4; r0 < NN; r0 += gridDim.x * 4) {
        int rload = r0 + rl;
        if (rload < NN) hs[rl][c] = g_h2[rload * D + c];
        __syncthreads();
        int r = r0 + rl;
        if (r < NN) {
            float acc = bs[c];
            #pragma unroll
            for (int k = 0; k < D; k++) acc += hs[rl][k] * Wt[k * D + c];
            out[r * D + c] = acc;
        }
        __syncthreads();
    }
}

extern "C" void kernel_launch(void* const* d_in, const int* in_sizes, int n_in,
                              void* d_out, int out_size) {
    const float* x  = (const float*)d_in[0];                 // [NN, D]
    const int*   ei = (const int*)d_in[1];                   // [2, NE]
    const float* W  = (const float*)d_in[2];                 // [D, D]
    const float* b  = (const float*)d_in[3];                 // [D]
    const int* src = ei;
    const int* dst = ei + NE;
    float* out = (float*)d_out;

    k_init_deg<<<(NN + 255) / 256, 256>>>();
    k_hist<<<(NE + 255) / 256, 256>>>(dst);
    k_dinv<<<(NN + 255) / 256, 256>>>();
    k_scan<<<1, 1024>>>();
    k_scatter<<<(NE + 255) / 256, 256>>>(src, dst);
    k_hop1<<<(NN * 32 + 255) / 256, 256>>>(x);
    k_hop2<<<(NN * 32 + 255) / 256, 256>>>();
    k_lin<<<2048, 256>>>(W, b, out);
}

// round 2
// speedup vs baseline: 1.6640x; 1.6640x over previous
#include <cuda_runtime.h>

#define NN 100000
#define NE 1000000
#define D  64
#define NB 98   // ceil(NN/1024)

// ---- device scratch (static, no allocation) ----
__device__ int   g_deg[NN];
__device__ float g_dinv[NN];
__device__ int   g_off[NN + 1];
__device__ int   g_pos[NN];
__device__ int   g_bsum[NB];
__device__ int   g_bex[NB];
__device__ int   g_csr_src[NE];
__device__ float g_h1[NN * D];
__device__ float g_h2[NN * D];

// 1) deg[i] = 1 (self loop)
__global__ void k_init_deg() {
    int i = blockIdx.x * blockDim.x + threadIdx.x;
    if (i < NN) g_deg[i] = 1;
}

// 2) histogram of in-degree over dst
__global__ void k_hist(const int* __restrict__ dst) {
    int e = blockIdx.x * blockDim.x + threadIdx.x;
    if (e < NE) atomicAdd(&g_deg[dst[e]], 1);
}

// 3) dinv = rsqrt(deg)
__global__ void k_dinv() {
    int i = blockIdx.x * blockDim.x + threadIdx.x;
    if (i < NN) g_dinv[i] = rsqrtf((float)g_deg[i]);
}

// 4a) per-block exclusive scan of (deg-1); block sums to g_bsum
__global__ void k_scan1() {
    __shared__ int wsum[32];
    int i = blockIdx.x * 1024 + threadIdx.x;
    int lane = threadIdx.x & 31, wid = threadIdx.x >> 5;
    int v = (i < NN) ? (g_deg[i] - 1) : 0;
    int s = v;
    #pragma unroll
    for (int d = 1; d < 32; d <<= 1) {
        int t = __shfl_up_sync(0xffffffffu, s, d);
        if (lane >= d) s += t;
    }
    if (lane == 31) wsum[wid] = s;
    __syncthreads();
    if (wid == 0) {
        int ws = wsum[lane];
        #pragma unroll
        for (int d = 1; d < 32; d <<= 1) {
            int t = __shfl_up_sync(0xffffffffu, ws, d);
            if (lane >= d) ws += t;
        }
        wsum[lane] = ws;
    }
    __syncthreads();
    int ex = s - v + (wid ? wsum[wid - 1] : 0);
    if (i < NN) g_off[i] = ex;                       // block-local exclusive
    if (threadIdx.x == 1023) g_bsum[blockIdx.x] = ex + v;
}

// 4b) exclusive scan of the 98 block sums (single warp-group block)
__global__ void k_scan2() {
    __shared__ int wsum[4];
    int lane = threadIdx.x & 31, wid = threadIdx.x >> 5;
    int v = (threadIdx.x < NB) ? g_bsum[threadIdx.x] : 0;
    int s = v;
    #pragma unroll
    for (int d = 1; d < 32; d <<= 1) {
        int t = __shfl_up_sync(0xffffffffu, s, d);
        if (lane >= d) s += t;
    }
    if (lane == 31) wsum[wid] = s;
    __syncthreads();
    int add = 0;
    for (int w = 0; w < wid; w++) add += wsum[w];
    if (threadIdx.x < NB) g_bex[threadIdx.x] = s + add - v;  // exclusive
}

// 4c) add block offsets; seed g_pos; g_off[NN] = NE (total is a constant)
__global__ void k_scan3() {
    int i = blockIdx.x * blockDim.x + threadIdx.x;
    if (i < NN) {
        int o = g_off[i] + g_bex[i >> 10];
        g_off[i] = o;
        g_pos[i] = o;
    }
    if (i == 0) g_off[NN] = NE;
}

// 5) scatter edge sources into CSR buckets by dst
__global__ void k_scatter(const int* __restrict__ src, const int* __restrict__ dst) {
    int e = blockIdx.x * blockDim.x + threadIdx.x;
    if (e < NE) {
        int d = dst[e];
        int p = atomicAdd(&g_pos[d], 1);
        g_csr_src[p] = src[e];
    }
}

// ---- hop body: warp per node, float2 per lane, 2-stage prefetch pipeline ----
__device__ __forceinline__ void hop_body(const float2* __restrict__ in2,
                                         float2* __restrict__ out2,
                                         int i, int lane) {
    float di = g_dinv[i];
    float2 a = __ldg(&in2[i * 32 + lane]);
    float2 acc;
    acc.x = di * di * a.x;
    acc.y = di * di * a.y;
    int beg = g_off[i], end = g_off[i + 1];
    if (beg < end) {
        int   s0 = __ldg(&g_csr_src[beg]);
        float w0 = __ldg(&g_dinv[s0]);
        float2 v0 = __ldg(&in2[s0 * 32 + lane]);
        for (int j = beg + 1; j < end; j++) {
            int   s1 = __ldg(&g_csr_src[j]);
            float w1 = __ldg(&g_dinv[s1]);
            float2 v1 = __ldg(&in2[s1 * 32 + lane]);
            float w = w0 * di;
            acc.x += w * v0.x;
            acc.y += w * v0.y;
            w0 = w1; v0 = v1;
        }
        float w = w0 * di;
        acc.x += w * v0.x;
        acc.y += w * v0.y;
    }
    out2[i * 32 + lane] = acc;
}

// 6) hop 1: g_h1 = A_hat * x
__global__ void k_hop1(const float* __restrict__ x) {
    int gw   = (blockIdx.x * blockDim.x + threadIdx.x) >> 5;
    int lane = threadIdx.x & 31;
    if (gw >= NN) return;
    hop_body((const float2*)x, (float2*)g_h1, gw, lane);
}

// 7) hop 2: g_h2 = A_hat * g_h1
__global__ void k_hop2() {
    int gw   = (blockIdx.x * blockDim.x + threadIdx.x) >> 5;
    int lane = threadIdx.x & 31;
    if (gw >= NN) return;
    hop_body((const float2*)g_h1, (float2*)g_h2, gw, lane);
}

// 8) out = g_h2 @ W^T + b
__global__ void k_lin(const float* __restrict__ W, const float* __restrict__ b,
                      float* __restrict__ out) {
    __shared__ float Wt[D * D];   // Wt[k*D + c] = W[c*D + k]
    __shared__ float bs[D];
    __shared__ float hs[4][D];
    for (int t = threadIdx.x; t < D * D; t += blockDim.x) {
        int c = t / D, k = t % D;
        Wt[k * D + c] = W[c * D + k];
    }
    if (threadIdx.x < D) bs[threadIdx.x] = b[threadIdx.x];
    __syncthreads();

    int rl = threadIdx.x / D;   // 0..3 (local row)
    int c  = threadIdx.x % D;   // output column

    for (int r0 = blockIdx.x * 4; r0 < NN; r0 += gridDim.x * 4) {
        int rload = r0 + rl;
        if (rload < NN) hs[rl][c] = g_h2[rload * D + c];
        __syncthreads();
        int r = r0 + rl;
        if (r < NN) {
            float acc = bs[c];
            #pragma unroll
            for (int k = 0; k < D; k++) acc += hs[rl][k] * Wt[k * D + c];
            out[r * D + c] = acc;
        }
        __syncthreads();
    }
}

extern "C" void kernel_launch(void* const* d_in, const int* in_sizes, int n_in,
                              void* d_out, int out_size) {
    const float* x  = (const float*)d_in[0];                 // [NN, D]
    const int*   ei = (const int*)d_in[1];                   // [2, NE]
    const float* W  = (const float*)d_in[2];                 // [D, D]
    const float* b  = (const float*)d_in[3];                 // [D]
    const int* src = ei;
    const int* dst = ei + NE;
    float* out = (float*)d_out;

    k_init_deg<<<(NN + 255) / 256, 256>>>();
    k_hist<<<(NE + 255) / 256, 256>>>(dst);
    k_dinv<<<(NN + 255) / 256, 256>>>();
    k_scan1<<<NB, 1024>>>();
    k_scan2<<<1, 128>>>();
    k_scan3<<<(NN + 255) / 256, 256>>>();
    k_scatter<<<(NE + 255) / 256, 256>>>(src, dst);
    k_hop1<<<(NN * 32 + 255) / 256, 256>>>(x);
    k_hop2<<<(NN * 32 + 255) / 256, 256>>>();
    k_lin<<<2048, 256>>>(W, b, out);
}

// round 4
// speedup vs baseline: 2.3036x; 1.3844x over previous
#include <cuda_runtime.h>

#define NN 100000
#define NE 1000000
#define D  64
#define NB 98   // ceil(NN/1024)

// ---- device scratch (static, no allocation) ----
__device__ int   g_deg[NN];
__device__ float g_dinv[NN];
__device__ int   g_off[NN + 1];
__device__ int   g_pos[NN];
__device__ int   g_bsum[NB];
__device__ int   g_bex[NB];
__device__ int   g_csr_src[NE];
__device__ float g_u0[NN * D];
__device__ float g_u1[NN * D];
__device__ float g_h2[NN * D];

// 1) deg[i] = 1 (self loop)
__global__ void k_init_deg() {
    int i = blockIdx.x * blockDim.x + threadIdx.x;
    if (i < NN) g_deg[i] = 1;
}

// 2) histogram of in-degree over dst
__global__ void k_hist(const int* __restrict__ dst) {
    int e = blockIdx.x * blockDim.x + threadIdx.x;
    if (e < NE) atomicAdd(&g_deg[dst[e]], 1);
}

// 3a) per-block exclusive scan of (deg-1); block sums; also dinv = rsqrt(deg)
__global__ void k_scan1() {
    __shared__ int wsum[32];
    int i = blockIdx.x * 1024 + threadIdx.x;
    int lane = threadIdx.x & 31, wid = threadIdx.x >> 5;
    int dg = (i < NN) ? g_deg[i] : 1;
    if (i < NN) g_dinv[i] = rsqrtf((float)dg);
    int v = (i < NN) ? (dg - 1) : 0;
    int s = v;
    #pragma unroll
    for (int d = 1; d < 32; d <<= 1) {
        int t = __shfl_up_sync(0xffffffffu, s, d);
        if (lane >= d) s += t;
    }
    if (lane == 31) wsum[wid] = s;
    __syncthreads();
    if (wid == 0) {
        int ws = wsum[lane];
        #pragma unroll
        for (int d = 1; d < 32; d <<= 1) {
            int t = __shfl_up_sync(0xffffffffu, ws, d);
            if (lane >= d) ws += t;
        }
        wsum[lane] = ws;
    }
    __syncthreads();
    int ex = s - v + (wid ? wsum[wid - 1] : 0);
    if (i < NN) g_off[i] = ex;                       // block-local exclusive
    if (threadIdx.x == 1023) g_bsum[blockIdx.x] = ex + v;
}

// 3b) exclusive scan of the 98 block sums
__global__ void k_scan2() {
    __shared__ int wsum[4];
    int lane = threadIdx.x & 31, wid = threadIdx.x >> 5;
    int v = (threadIdx.x < NB) ? g_bsum[threadIdx.x] : 0;
    int s = v;
    #pragma unroll
    for (int d = 1; d < 32; d <<= 1) {
        int t = __shfl_up_sync(0xffffffffu, s, d);
        if (lane >= d) s += t;
    }
    if (lane == 31) wsum[wid] = s;
    __syncthreads();
    int add = 0;
    for (int w = 0; w < wid; w++) add += wsum[w];
    if (threadIdx.x < NB) g_bex[threadIdx.x] = s + add - v;  // exclusive
}

// 3c) add block offsets; seed g_pos
__global__ void k_scan3() {
    int i = blockIdx.x * blockDim.x + threadIdx.x;
    if (i < NN) {
        int o = g_off[i] + g_bex[i >> 10];
        g_off[i] = o;
        g_pos[i] = o;
    }
    if (i == 0) g_off[NN] = NE;
}

// 4) scatter edge sources into CSR buckets by dst (unweighted)
__global__ void k_scatter(const int* __restrict__ src, const int* __restrict__ dst) {
    int e = blockIdx.x * blockDim.x + threadIdx.x;
    if (e < NE) {
        int d = dst[e];
        int p = atomicAdd(&g_pos[d], 1);
        g_csr_src[p] = src[e];
    }
}

// 5) u0 = dinv .* x
__global__ void k_prep(const float* __restrict__ x) {
    int t = blockIdx.x * blockDim.x + threadIdx.x;   // over NN*32 float2
    if (t < NN * 32) {
        int i = t >> 5;
        float di = g_dinv[i];
        float2 v = ((const float2*)x)[t];
        float2 o; o.x = di * v.x; o.y = di * v.y;
        ((float2*)g_u0)[t] = o;
    }
}

// ---- hop: warp per node, unweighted row-sum gather, index chunks in regs ----
// PASS 0: in = g_u0, out = g_u1, scale = dinv^2
// PASS 1: in = g_u1, out = g_h2, scale = dinv
template <int PASS>
__global__ void k_hop() {
    const float2* __restrict__ in2 =
        (PASS == 0) ? (const float2*)g_u0 : (const float2*)g_u1;
    float2* __restrict__ out2 =
        (PASS == 0) ? (float2*)g_u1 : (float2*)g_h2;

    int gw   = (blockIdx.x * blockDim.x + threadIdx.x) >> 5;
    int lane = threadIdx.x & 31;
    if (gw >= NN) return;
    const int i = gw;
    float2 acc = __ldg(&in2[i * 32 + lane]);   // self term (raw u)
    int beg = g_off[i], end = g_off[i + 1];
    for (int c = beg; c < end; c += 32) {
        int n = end - c; if (n > 32) n = 32;
        int myS = (c + lane < end) ? __ldg(&g_csr_src[c + lane]) : 0;
        int k = 0;
        for (; k + 4 <= n; k += 4) {
            int s0 = __shfl_sync(0xffffffffu, myS, k + 0);
            int s1 = __shfl_sync(0xffffffffu, myS, k + 1);
            int s2 = __shfl_sync(0xffffffffu, myS, k + 2);
            int s3 = __shfl_sync(0xffffffffu, myS, k + 3);
            float2 v0 = __ldg(&in2[s0 * 32 + lane]);
            float2 v1 = __ldg(&in2[s1 * 32 + lane]);
            float2 v2 = __ldg(&in2[s2 * 32 + lane]);
            float2 v3 = __ldg(&in2[s3 * 32 + lane]);
            acc.x += v0.x; acc.y += v0.y;
            acc.x += v1.x; acc.y += v1.y;
            acc.x += v2.x; acc.y += v2.y;
            acc.x += v3.x; acc.y += v3.y;
        }
        for (; k < n; k++) {
            int s = __shfl_sync(0xffffffffu, myS, k);
            float2 v = __ldg(&in2[s * 32 + lane]);
            acc.x += v.x; acc.y += v.y;
        }
    }
    float di = g_dinv[i];
    float sc = (PASS == 0) ? di * di : di;
    acc.x *= sc; acc.y *= sc;
    out2[i * 32 + lane] = acc;
}

// 6) out = g_h2 @ W^T + b  (packed fma.rn.f32x2: 2 cols x 4 rows per thread)
__global__ void k_lin(const float* __restrict__ W, const float* __restrict__ b,
                      float* __restrict__ out) {
    __shared__ unsigned long long Wp[D * 32];   // Wp[k*32+c2] = (W[2c2][k], W[2c2+1][k])
    __shared__ float hs[32 * D];                // 32 staged rows
    __shared__ unsigned long long bp[32];

    for (int t = threadIdx.x; t < D * 32; t += 256) {
        int k = t >> 5, c2 = t & 31;
        float lo = W[(2 * c2) * D + k];
        float hi = W[(2 * c2 + 1) * D + k];
        unsigned long long u;
        asm("mov.b64 %0, {%1, %2};" : "=l"(u) : "f"(lo), "f"(hi));
        Wp[t] = u;
    }
    if (threadIdx.x < 32) {
        unsigned long long u;
        asm("mov.b64 %0, {%1, %2};" : "=l"(u)
            : "f"(b[2 * threadIdx.x]), "f"(b[2 * threadIdx.x + 1]));
        bp[threadIdx.x] = u;
    }
    __syncthreads();

    int wid = threadIdx.x >> 5, lane = threadIdx.x & 31;

    for (int r0 = blockIdx.x * 32; r0 < NN; r0 += gridDim.x * 32) {
        const float2* src = (const float2*)g_h2 + r0 * 32;
        #pragma unroll
        for (int t = threadIdx.x; t < 1024; t += 256)
            ((float2*)hs)[t] = src[t];
        __syncthreads();

        unsigned long long a0 = bp[lane], a1 = a0, a2 = a0, a3 = a0;
        const float* h0 = &hs[(wid * 4 + 0) * D];
        const float* h1 = &hs[(wid * 4 + 1) * D];
        const float* h2 = &hs[(wid * 4 + 2) * D];
        const float* h3 = &hs[(wid * 4 + 3) * D];
        #pragma unroll
        for (int k = 0; k < D; k++) {
            unsigned long long wv = Wp[k * 32 + lane];
            float v0 = h0[k], v1 = h1[k], v2 = h2[k], v3 = h3[k];
            unsigned long long p0, p1, p2, p3;
            asm("mov.b64 %0, {%1, %1};" : "=l"(p0) : "f"(v0));
            asm("mov.b64 %0, {%1, %1};" : "=l"(p1) : "f"(v1));
            asm("mov.b64 %0, {%1, %1};" : "=l"(p2) : "f"(v2));
            asm("mov.b64 %0, {%1, %1};" : "=l"(p3) : "f"(v3));
            asm("fma.rn.f32x2 %0, %1, %2, %3;" : "=l"(a0) : "l"(p0), "l"(wv), "l"(a0));
            asm("fma.rn.f32x2 %0, %1, %2, %3;" : "=l"(a1) : "l"(p1), "l"(wv), "l"(a1));
            asm("fma.rn.f32x2 %0, %1, %2, %3;" : "=l"(a2) : "l"(p2), "l"(wv), "l"(a2));
            asm("fma.rn.f32x2 %0, %1, %2, %3;" : "=l"(a3) : "l"(p3), "l"(wv), "l"(a3));
        }
        int r = r0 + wid * 4;
        unsigned long long* o = (unsigned long long*)out;
        o[(r + 0) * 32 + lane] = a0;
        o[(r + 1) * 32 + lane] = a1;
        o[(r + 2) * 32 + lane] = a2;
        o[(r + 3) * 32 + lane] = a3;
        __syncthreads();
    }
}

extern "C" void kernel_launch(void* const* d_in, const int* in_sizes, int n_in,
                              void* d_out, int out_size) {
    const float* x  = (const float*)d_in[0];                 // [NN, D]
    const int*   ei = (const int*)d_in[1];                   // [2, NE]
    const float* W  = (const float*)d_in[2];                 // [D, D]
    const float* b  = (const float*)d_in[3];                 // [D]
    const int* src = ei;
    const int* dst = ei + NE;
    float* out = (float*)d_out;

    k_init_deg<<<(NN + 255) / 256, 256>>>();
    k_hist<<<(NE + 255) / 256, 256>>>(dst);
    k_scan1<<<NB, 1024>>>();
    k_scan2<<<1, 128>>>();
    k_scan3<<<(NN + 255) / 256, 256>>>();
    k_scatter<<<(NE + 255) / 256, 256>>>(src, dst);
    k_prep<<<(NN * 32 + 255) / 256, 256>>>(x);
    k_hop<0><<<(NN * 32 + 255) / 256, 256>>>();
    k_hop<1><<<(NN * 32 + 255) / 256, 256>>>();
    k_lin<<<1184, 256>>>(W, b, out);
}

// round 5
// speedup vs baseline: 2.3149x; 1.0049x over previous
#include <cuda_runtime.h>

#define NN 100000
#define NE 1000000
#define D  64
#define NB 98   // ceil(NN/1024)

// ---- device scratch (static, no allocation) ----
__device__ int   g_deg[NN];        // edge-count (self loop added in math)
__device__ float g_dinv[NN];
__device__ int   g_off[NN + 1];
__device__ int   g_pos[NN];
__device__ int   g_bsum[NB];
__device__ int   g_csr_src[NE];
__device__ float g_u0[NN * D];
__device__ float g_u1[NN * D];
__device__ float g_h2[NN * D];

// 1) histogram of in-degree over dst (g_deg pre-zeroed by memset node)
__global__ void k_hist(const int* __restrict__ dst) {
    int e = blockIdx.x * blockDim.x + threadIdx.x;
    if (e < NE) atomicAdd(&g_deg[dst[e]], 1);
}

// 2) per-block exclusive scan of edge-counts; block sums; dinv = rsqrt(deg+1)
__global__ void k_scan1() {
    __shared__ int wsum[32];
    int i = blockIdx.x * 1024 + threadIdx.x;
    int lane = threadIdx.x & 31, wid = threadIdx.x >> 5;
    int v = (i < NN) ? g_deg[i] : 0;            // edges into i
    if (i < NN) g_dinv[i] = rsqrtf((float)(v + 1));
    int s = v;
    #pragma unroll
    for (int d = 1; d < 32; d <<= 1) {
        int t = __shfl_up_sync(0xffffffffu, s, d);
        if (lane >= d) s += t;
    }
    if (lane == 31) wsum[wid] = s;
    __syncthreads();
    if (wid == 0) {
        int ws = wsum[lane];
        #pragma unroll
        for (int d = 1; d < 32; d <<= 1) {
            int t = __shfl_up_sync(0xffffffffu, ws, d);
            if (lane >= d) ws += t;
        }
        wsum[lane] = ws;
    }
    __syncthreads();
    int ex = s - v + (wid ? wsum[wid - 1] : 0);
    if (i < NN) g_off[i] = ex;                  // block-local exclusive
    if (threadIdx.x == 1023) g_bsum[blockIdx.x] = ex + v;
}

// 3) per-block: add block offset (self-computed), seed g_pos, and u0 = dinv.*x
__global__ void k_scan23(const float* __restrict__ x) {
    __shared__ int sh_bex;
    if (threadIdx.x < 32) {
        int v = 0;
        for (int j = threadIdx.x; j < blockIdx.x; j += 32) v += g_bsum[j];
        #pragma unroll
        for (int d = 16; d; d >>= 1) v += __shfl_down_sync(0xffffffffu, v, d);
        if (threadIdx.x == 0) sh_bex = v;
    }
    __syncthreads();
    int i = blockIdx.x * 1024 + threadIdx.x;
    if (i < NN) {
        int o = g_off[i] + sh_bex;
        g_off[i] = o;
        g_pos[i] = o;
    }
    if (i == 0) g_off[NN] = NE;
    // fused prep for this block's node range
    int base = blockIdx.x * 1024 * 32;          // float2 index
    const float2* x2 = (const float2*)x;
    float2* u02 = (float2*)g_u0;
    #pragma unroll 4
    for (int t = threadIdx.x; t < 1024 * 32; t += 1024) {
        int idx = base + t;
        if (idx < NN * 32) {
            float di = g_dinv[idx >> 5];
            float2 v = __ldg(&x2[idx]);
            float2 o; o.x = di * v.x; o.y = di * v.y;
            u02[idx] = o;
        }
    }
}

// 4) scatter edge sources into CSR buckets by dst
__global__ void k_scatter(const int* __restrict__ src, const int* __restrict__ dst) {
    int e = blockIdx.x * blockDim.x + threadIdx.x;
    if (e < NE) {
        int d = dst[e];
        int p = atomicAdd(&g_pos[d], 1);
        g_csr_src[p] = src[e];
    }
}

// ---- hop: warp per node, unweighted row-sum gather, 8-deep load pipeline ----
// PASS 0: in = g_u0, out = g_u1, scale = dinv^2
// PASS 1: in = g_u1, out = g_h2, scale = dinv
template <int PASS>
__global__ void k_hop() {
    const float2* __restrict__ in2 =
        (PASS == 0) ? (const float2*)g_u0 : (const float2*)g_u1;
    float2* __restrict__ out2 =
        (PASS == 0) ? (float2*)g_u1 : (float2*)g_h2;

    int gw   = (blockIdx.x * blockDim.x + threadIdx.x) >> 5;
    int lane = threadIdx.x & 31;
    if (gw >= NN) return;
    const int i = gw;
    float2 acc = __ldg(&in2[i * 32 + lane]);   // self term (raw u)
    int beg = g_off[i], end = g_off[i + 1];
    for (int c = beg; c < end; c += 32) {
        int n = end - c; if (n > 32) n = 32;
        int myS = (c + lane < end) ? __ldg(&g_csr_src[c + lane]) : 0;
        int k = 0;
        for (; k + 8 <= n; k += 8) {
            int s0 = __shfl_sync(0xffffffffu, myS, k + 0);
            int s1 = __shfl_sync(0xffffffffu, myS, k + 1);
            int s2 = __shfl_sync(0xffffffffu, myS, k + 2);
            int s3 = __shfl_sync(0xffffffffu, myS, k + 3);
            int s4 = __shfl_sync(0xffffffffu, myS, k + 4);
            int s5 = __shfl_sync(0xffffffffu, myS, k + 5);
            int s6 = __shfl_sync(0xffffffffu, myS, k + 6);
            int s7 = __shfl_sync(0xffffffffu, myS, k + 7);
            float2 v0 = __ldg(&in2[s0 * 32 + lane]);
            float2 v1 = __ldg(&in2[s1 * 32 + lane]);
            float2 v2 = __ldg(&in2[s2 * 32 + lane]);
            float2 v3 = __ldg(&in2[s3 * 32 + lane]);
            float2 v4 = __ldg(&in2[s4 * 32 + lane]);
            float2 v5 = __ldg(&in2[s5 * 32 + lane]);
            float2 v6 = __ldg(&in2[s6 * 32 + lane]);
            float2 v7 = __ldg(&in2[s7 * 32 + lane]);
            acc.x += v0.x; acc.y += v0.y;
            acc.x += v1.x; acc.y += v1.y;
            acc.x += v2.x; acc.y += v2.y;
            acc.x += v3.x; acc.y += v3.y;
            acc.x += v4.x; acc.y += v4.y;
            acc.x += v5.x; acc.y += v5.y;
            acc.x += v6.x; acc.y += v6.y;
            acc.x += v7.x; acc.y += v7.y;
        }
        for (; k + 2 <= n; k += 2) {
            int s0 = __shfl_sync(0xffffffffu, myS, k + 0);
            int s1 = __shfl_sync(0xffffffffu, myS, k + 1);
            float2 v0 = __ldg(&in2[s0 * 32 + lane]);
            float2 v1 = __ldg(&in2[s1 * 32 + lane]);
            acc.x += v0.x; acc.y += v0.y;
            acc.x += v1.x; acc.y += v1.y;
        }
        if (k < n) {
            int s = __shfl_sync(0xffffffffu, myS, k);
            float2 v = __ldg(&in2[s * 32 + lane]);
            acc.x += v.x; acc.y += v.y;
        }
    }
    float di = g_dinv[i];
    float sc = (PASS == 0) ? di * di : di;
    acc.x *= sc; acc.y *= sc;
    out2[i * 32 + lane] = acc;
}

// 5) out = g_h2 @ W^T + b  (packed fma.rn.f32x2: 2 cols x 4 rows per thread)
__global__ void k_lin(const float* __restrict__ W, const float* __restrict__ b,
                      float* __restrict__ out) {
    __shared__ unsigned long long Wp[D * 32];   // Wp[k*32+c2] = (W[2c2][k], W[2c2+1][k])
    __shared__ float hs[32 * D];                // 32 staged rows
    __shared__ unsigned long long bp[32];

    for (int t = threadIdx.x; t < D * 32; t += 256) {
        int k = t >> 5, c2 = t & 31;
        float lo = W[(2 * c2) * D + k];
        float hi = W[(2 * c2 + 1) * D + k];
        unsigned long long u;
        asm("mov.b64 %0, {%1, %2};" : "=l"(u) : "f"(lo), "f"(hi));
        Wp[t] = u;
    }
    if (threadIdx.x < 32) {
        unsigned long long u;
        asm("mov.b64 %0, {%1, %2};" : "=l"(u)
            : "f"(b[2 * threadIdx.x]), "f"(b[2 * threadIdx.x + 1]));
        bp[threadIdx.x] = u;
    }
    __syncthreads();

    int wid = threadIdx.x >> 5, lane = threadIdx.x & 31;

    for (int r0 = blockIdx.x * 32; r0 < NN; r0 += gridDim.x * 32) {
        const float2* src = (const float2*)g_h2 + r0 * 32;
        #pragma unroll
        for (int t = threadIdx.x; t < 1024; t += 256)
            ((float2*)hs)[t] = src[t];
        __syncthreads();

        unsigned long long a0 = bp[lane], a1 = a0, a2 = a0, a3 = a0;
        const float* h0 = &hs[(wid * 4 + 0) * D];
        const float* h1 = &hs[(wid * 4 + 1) * D];
        const float* h2 = &hs[(wid * 4 + 2) * D];
        const float* h3 = &hs[(wid * 4 + 3) * D];
        #pragma unroll
        for (int k = 0; k < D; k++) {
            unsigned long long wv = Wp[k * 32 + lane];
            float v0 = h0[k], v1 = h1[k], v2 = h2[k], v3 = h3[k];
            unsigned long long p0, p1, p2, p3;
            asm("mov.b64 %0, {%1, %1};" : "=l"(p0) : "f"(v0));
            asm("mov.b64 %0, {%1, %1};" : "=l"(p1) : "f"(v1));
            asm("mov.b64 %0, {%1, %1};" : "=l"(p2) : "f"(v2));
            asm("mov.b64 %0, {%1, %1};" : "=l"(p3) : "f"(v3));
            asm("fma.rn.f32x2 %0, %1, %2, %3;" : "=l"(a0) : "l"(p0), "l"(wv), "l"(a0));
            asm("fma.rn.f32x2 %0, %1, %2, %3;" : "=l"(a1) : "l"(p1), "l"(wv), "l"(a1));
            asm("fma.rn.f32x2 %0, %1, %2, %3;" : "=l"(a2) : "l"(p2), "l"(wv), "l"(a2));
            asm("fma.rn.f32x2 %0, %1, %2, %3;" : "=l"(a3) : "l"(p3), "l"(wv), "l"(a3));
        }
        int r = r0 + wid * 4;
        unsigned long long* o = (unsigned long long*)out;
        o[(r + 0) * 32 + lane] = a0;
        o[(r + 1) * 32 + lane] = a1;
        o[(r + 2) * 32 + lane] = a2;
        o[(r + 3) * 32 + lane] = a3;
        __syncthreads();
    }
}

extern "C" void kernel_launch(void* const* d_in, const int* in_sizes, int n_in,
                              void* d_out, int out_size) {
    const float* x  = (const float*)d_in[0];                 // [NN, D]
    const int*   ei = (const int*)d_in[1];                   // [2, NE]
    const float* W  = (const float*)d_in[2];                 // [D, D]
    const float* b  = (const float*)d_in[3];                 // [D]
    const int* src = ei;
    const int* dst = ei + NE;
    float* out = (float*)d_out;

    void* deg_ptr = nullptr;
    cudaGetSymbolAddress(&deg_ptr, g_deg);
    cudaMemsetAsync(deg_ptr, 0, NN * sizeof(int));           // memset graph node

    k_hist<<<(NE + 255) / 256, 256>>>(dst);                  // launch 0
    k_scan1<<<NB, 1024>>>();                                 // launch 1
    k_scan23<<<NB, 1024>>>(x);                               // launch 2
    k_scatter<<<(NE + 255) / 256, 256>>>(src, dst);          // launch 3
    k_hop<0><<<(NN * 32 + 255) / 256, 256>>>();              // launch 4
    k_hop<1><<<(NN * 32 + 255) / 256, 256>>>();              // launch 5 (ncu -s 5)
    k_lin<<<1184, 256>>>(W, b, out);                         // launch 6
}

// round 6
// speedup vs baseline: 2.3741x; 1.0256x over previous
#include <cuda_runtime.h>
#include <cuda_fp16.h>

#define NN 100000
#define NE 1000000
#define D  64
#define NB 98   // ceil(NN/1024)

// ---- device scratch (static, no allocation) ----
__device__ int     g_deg[NN];        // edge-count (self loop added in math)
__device__ float   g_dinv[NN];
__device__ int     g_off[NN + 1];
__device__ int     g_pos[NN];
__device__ int     g_bsum[NB];
__device__ int     g_csr_src[NE];
__device__ __half  g_u0[NN * D];     // fp16 intermediates
__device__ __half  g_u1[NN * D];
__device__ float   g_h2[NN * D];

// 1) histogram of in-degree over dst (g_deg pre-zeroed by memset node)
__global__ void k_hist(const int* __restrict__ dst) {
    int e = blockIdx.x * blockDim.x + threadIdx.x;
    if (e < NE) atomicAdd(&g_deg[dst[e]], 1);
}

// 2) per-block exclusive scan of edge-counts; block sums; dinv = rsqrt(deg+1)
__global__ void k_scan1() {
    __shared__ int wsum[32];
    int i = blockIdx.x * 1024 + threadIdx.x;
    int lane = threadIdx.x & 31, wid = threadIdx.x >> 5;
    int v = (i < NN) ? g_deg[i] : 0;            // edges into i
    if (i < NN) g_dinv[i] = rsqrtf((float)(v + 1));
    int s = v;
    #pragma unroll
    for (int d = 1; d < 32; d <<= 1) {
        int t = __shfl_up_sync(0xffffffffu, s, d);
        if (lane >= d) s += t;
    }
    if (lane == 31) wsum[wid] = s;
    __syncthreads();
    if (wid == 0) {
        int ws = wsum[lane];
        #pragma unroll
        for (int d = 1; d < 32; d <<= 1) {
            int t = __shfl_up_sync(0xffffffffu, ws, d);
            if (lane >= d) ws += t;
        }
        wsum[lane] = ws;
    }
    __syncthreads();
    int ex = s - v + (wid ? wsum[wid - 1] : 0);
    if (i < NN) g_off[i] = ex;                  // block-local exclusive
    if (threadIdx.x == 1023) g_bsum[blockIdx.x] = ex + v;
}

// 3) per-block: add block offset (self-computed), seed g_pos, and u0 = fp16(dinv.*x)
__global__ void k_scan23(const float* __restrict__ x) {
    __shared__ int sh_bex;
    if (threadIdx.x < 32) {
        int v = 0;
        for (int j = threadIdx.x; j < blockIdx.x; j += 32) v += g_bsum[j];
        #pragma unroll
        for (int d = 16; d; d >>= 1) v += __shfl_down_sync(0xffffffffu, v, d);
        if (threadIdx.x == 0) sh_bex = v;
    }
    __syncthreads();
    int i = blockIdx.x * 1024 + threadIdx.x;
    if (i < NN) {
        int o = g_off[i] + sh_bex;
        g_off[i] = o;
        g_pos[i] = o;
    }
    if (i == 0) g_off[NN] = NE;
    // fused prep for this block's node range (float2 in -> half2 out)
    int base = blockIdx.x * 1024 * 32;          // element-pair index
    const float2* x2 = (const float2*)x;
    __half2* u02 = (__half2*)g_u0;
    #pragma unroll 4
    for (int t = threadIdx.x; t < 1024 * 32; t += 1024) {
        int idx = base + t;
        if (idx < NN * 32) {
            float di = g_dinv[idx >> 5];
            float2 v = __ldg(&x2[idx]);
            float2 o; o.x = di * v.x; o.y = di * v.y;
            u02[idx] = __float22half2_rn(o);
        }
    }
}

// 4) scatter edge sources into CSR buckets by dst
__global__ void k_scatter(const int* __restrict__ src, const int* __restrict__ dst) {
    int e = blockIdx.x * blockDim.x + threadIdx.x;
    if (e < NE) {
        int d = dst[e];
        int p = atomicAdd(&g_pos[d], 1);
        g_csr_src[p] = src[e];
    }
}

// ---- hop: warp per node, fp16 row-sum gather, fp32 accumulation ----
// PASS 0: in = g_u0 (fp16), out = g_u1 (fp16), scale = dinv^2
// PASS 1: in = g_u1 (fp16), out = g_h2 (fp32), scale = dinv
template <int PASS>
__global__ void k_hop() {
    const __half2* __restrict__ in2 =
        (PASS == 0) ? (const __half2*)g_u0 : (const __half2*)g_u1;

    int gw   = (blockIdx.x * blockDim.x + threadIdx.x) >> 5;
    int lane = threadIdx.x & 31;
    if (gw >= NN) return;
    const int i = gw;
    float2 acc = __half22float2(__ldg(&in2[i * 32 + lane]));   // self term
    int beg = g_off[i], end = g_off[i + 1];
    for (int c = beg; c < end; c += 32) {
        int n = end - c; if (n > 32) n = 32;
        int myS = (c + lane < end) ? __ldg(&g_csr_src[c + lane]) : 0;
        int k = 0;
        for (; k + 8 <= n; k += 8) {
            int s0 = __shfl_sync(0xffffffffu, myS, k + 0);
            int s1 = __shfl_sync(0xffffffffu, myS, k + 1);
            int s2 = __shfl_sync(0xffffffffu, myS, k + 2);
            int s3 = __shfl_sync(0xffffffffu, myS, k + 3);
            int s4 = __shfl_sync(0xffffffffu, myS, k + 4);
            int s5 = __shfl_sync(0xffffffffu, myS, k + 5);
            int s6 = __shfl_sync(0xffffffffu, myS, k + 6);
            int s7 = __shfl_sync(0xffffffffu, myS, k + 7);
            __half2 v0 = __ldg(&in2[s0 * 32 + lane]);
            __half2 v1 = __ldg(&in2[s1 * 32 + lane]);
            __half2 v2 = __ldg(&in2[s2 * 32 + lane]);
            __half2 v3 = __ldg(&in2[s3 * 32 + lane]);
            __half2 v4 = __ldg(&in2[s4 * 32 + lane]);
            __half2 v5 = __ldg(&in2[s5 * 32 + lane]);
            __half2 v6 = __ldg(&in2[s6 * 32 + lane]);
            __half2 v7 = __ldg(&in2[s7 * 32 + lane]);
            float2 f0 = __half22float2(v0), f1 = __half22float2(v1);
            float2 f2 = __half22float2(v2), f3 = __half22float2(v3);
            float2 f4 = __half22float2(v4), f5 = __half22float2(v5);
            float2 f6 = __half22float2(v6), f7 = __half22float2(v7);
            acc.x += f0.x; acc.y += f0.y;
            acc.x += f1.x; acc.y += f1.y;
            acc.x += f2.x; acc.y += f2.y;
            acc.x += f3.x; acc.y += f3.y;
            acc.x += f4.x; acc.y += f4.y;
            acc.x += f5.x; acc.y += f5.y;
            acc.x += f6.x; acc.y += f6.y;
            acc.x += f7.x; acc.y += f7.y;
        }
        for (; k + 2 <= n; k += 2) {
            int s0 = __shfl_sync(0xffffffffu, myS, k + 0);
            int s1 = __shfl_sync(0xffffffffu, myS, k + 1);
            float2 f0 = __half22float2(__ldg(&in2[s0 * 32 + lane]));
            float2 f1 = __half22float2(__ldg(&in2[s1 * 32 + lane]));
            acc.x += f0.x; acc.y += f0.y;
            acc.x += f1.x; acc.y += f1.y;
        }
        if (k < n) {
            int s = __shfl_sync(0xffffffffu, myS, k);
            float2 f = __half22float2(__ldg(&in2[s * 32 + lane]));
            acc.x += f.x; acc.y += f.y;
        }
    }
    float di = g_dinv[i];
    if (PASS == 0) {
        float sc = di * di;
        acc.x *= sc; acc.y *= sc;
        ((__half2*)g_u1)[i * 32 + lane] = __float22half2_rn(acc);
    } else {
        acc.x *= di; acc.y *= di;
        ((float2*)g_h2)[i * 32 + lane] = acc;
    }
}

// 5) out = g_h2 @ W^T + b  (packed fma.rn.f32x2: 2 cols x 4 rows per thread)
__global__ void k_lin(const float* __restrict__ W, const float* __restrict__ b,
                      float* __restrict__ out) {
    __shared__ unsigned long long Wp[D * 32];   // Wp[k*32+c2] = (W[2c2][k], W[2c2+1][k])
    __shared__ float hs[32 * D];                // 32 staged rows
    __shared__ unsigned long long bp[32];

    for (int t = threadIdx.x; t < D * 32; t += 256) {
        int k = t >> 5, c2 = t & 31;
        float lo = W[(2 * c2) * D + k];
        float hi = W[(2 * c2 + 1) * D + k];
        unsigned long long u;
        asm("mov.b64 %0, {%1, %2};" : "=l"(u) : "f"(lo), "f"(hi));
        Wp[t] = u;
    }
    if (threadIdx.x < 32) {
        unsigned long long u;
        asm("mov.b64 %0, {%1, %2};" : "=l"(u)
            : "f"(b[2 * threadIdx.x]), "f"(b[2 * threadIdx.x + 1]));
        bp[threadIdx.x] = u;
    }
    __syncthreads();

    int wid = threadIdx.x >> 5, lane = threadIdx.x & 31;

    for (int r0 = blockIdx.x * 32; r0 < NN; r0 += gridDim.x * 32) {
        const float2* src = (const float2*)g_h2 + r0 * 32;
        #pragma unroll
        for (int t = threadIdx.x; t < 1024; t += 256)
            ((float2*)hs)[t] = src[t];
        __syncthreads();

        unsigned long long a0 = bp[lane], a1 = a0, a2 = a0, a3 = a0;
        const float* h0 = &hs[(wid * 4 + 0) * D];
        const float* h1 = &hs[(wid * 4 + 1) * D];
        const float* h2 = &hs[(wid * 4 + 2) * D];
        const float* h3 = &hs[(wid * 4 + 3) * D];
        #pragma unroll
        for (int k = 0; k < D; k++) {
            unsigned long long wv = Wp[k * 32 + lane];
            float v0 = h0[k], v1 = h1[k], v2 = h2[k], v3 = h3[k];
            unsigned long long p0, p1, p2, p3;
            asm("mov.b64 %0, {%1, %1};" : "=l"(p0) : "f"(v0));
            asm("mov.b64 %0, {%1, %1};" : "=l"(p1) : "f"(v1));
            asm("mov.b64 %0, {%1, %1};" : "=l"(p2) : "f"(v2));
            asm("mov.b64 %0, {%1, %1};" : "=l"(p3) : "f"(v3));
            asm("fma.rn.f32x2 %0, %1, %2, %3;" : "=l"(a0) : "l"(p0), "l"(wv), "l"(a0));
            asm("fma.rn.f32x2 %0, %1, %2, %3;" : "=l"(a1) : "l"(p1), "l"(wv), "l"(a1));
            asm("fma.rn.f32x2 %0, %1, %2, %3;" : "=l"(a2) : "l"(p2), "l"(wv), "l"(a2));
            asm("fma.rn.f32x2 %0, %1, %2, %3;" : "=l"(a3) : "l"(p3), "l"(wv), "l"(a3));
        }
        int r = r0 + wid * 4;
        unsigned long long* o = (unsigned long long*)out;
        o[(r + 0) * 32 + lane] = a0;
        o[(r + 1) * 32 + lane] = a1;
        o[(r + 2) * 32 + lane] = a2;
        o[(r + 3) * 32 + lane] = a3;
        __syncthreads();
    }
}

extern "C" void kernel_launch(void* const* d_in, const int* in_sizes, int n_in,
                              void* d_out, int out_size) {
    const float* x  = (const float*)d_in[0];                 // [NN, D]
    const int*   ei = (const int*)d_in[1];                   // [2, NE]
    const float* W  = (const float*)d_in[2];                 // [D, D]
    const float* b  = (const float*)d_in[3];                 // [D]
    const int* src = ei;
    const int* dst = ei + NE;
    float* out = (float*)d_out;

    void* deg_ptr = nullptr;
    cudaGetSymbolAddress(&deg_ptr, g_deg);
    cudaMemsetAsync(deg_ptr, 0, NN * sizeof(int));           // memset graph node

    k_hist<<<(NE + 255) / 256, 256>>>(dst);
    k_scan1<<<NB, 1024>>>();
    k_scan23<<<NB, 1024>>>(x);
    k_scatter<<<(NE + 255) / 256, 256>>>(src, dst);
    k_hop<0><<<(NN * 32 + 255) / 256, 256>>>();
    k_hop<1><<<(NN * 32 + 255) / 256, 256>>>();
    k_lin<<<1184, 256>>>(W, b, out);
}

// round 7
// speedup vs baseline: 2.4110x; 1.0155x over previous
#include <cuda_runtime.h>
#include <cuda_fp16.h>

#define NN 100000
#define NE 1000000
#define D  64
#define NB 98   // ceil(NN/1024)

// ---- device scratch (static, no allocation) ----
__device__ int     g_deg[NN];        // edge-count (self loop added in math)
__device__ float   g_dinv[NN];
__device__ int     g_off[NN + 1];
__device__ int     g_bsum[NB];
__device__ int     g_ppos[NE];       // per-edge rank within its dst bucket
__device__ int     g_csr_src[NE];
__device__ __half  g_u0[NN * D];     // fp16 intermediates
__device__ __half  g_u1[NN * D];
__device__ __half  g_h2[NN * D];

// 1) histogram of in-degree over dst; record each edge's bucket rank
__global__ void k_hist(const int* __restrict__ dst) {
    int e = blockIdx.x * blockDim.x + threadIdx.x;
    if (e < NE) g_ppos[e] = atomicAdd(&g_deg[dst[e]], 1);
}

// 2) per-block exclusive scan of edge-counts; block sums; dinv = rsqrt(deg+1)
__global__ void k_scan1() {
    __shared__ int wsum[32];
    int i = blockIdx.x * 1024 + threadIdx.x;
    int lane = threadIdx.x & 31, wid = threadIdx.x >> 5;
    int v = (i < NN) ? g_deg[i] : 0;            // edges into i
    if (i < NN) g_dinv[i] = rsqrtf((float)(v + 1));
    int s = v;
    #pragma unroll
    for (int d = 1; d < 32; d <<= 1) {
        int t = __shfl_up_sync(0xffffffffu, s, d);
        if (lane >= d) s += t;
    }
    if (lane == 31) wsum[wid] = s;
    __syncthreads();
    if (wid == 0) {
        int ws = wsum[lane];
        #pragma unroll
        for (int d = 1; d < 32; d <<= 1) {
            int t = __shfl_up_sync(0xffffffffu, ws, d);
            if (lane >= d) ws += t;
        }
        wsum[lane] = ws;
    }
    __syncthreads();
    int ex = s - v + (wid ? wsum[wid - 1] : 0);
    if (i < NN) g_off[i] = ex;                  // block-local exclusive
    if (threadIdx.x == 1023) g_bsum[blockIdx.x] = ex + v;
}

// 3) per-block: add block offset (self-computed) and u0 = fp16(dinv.*x)
__global__ void k_scan23(const float* __restrict__ x) {
    __shared__ int sh_bex;
    if (threadIdx.x < 32) {
        int v = 0;
        for (int j = threadIdx.x; j < blockIdx.x; j += 32) v += g_bsum[j];
        #pragma unroll
        for (int d = 16; d; d >>= 1) v += __shfl_down_sync(0xffffffffu, v, d);
        if (threadIdx.x == 0) sh_bex = v;
    }
    __syncthreads();
    int i = blockIdx.x * 1024 + threadIdx.x;
    if (i < NN) g_off[i] += sh_bex;
    if (i == 0) g_off[NN] = NE;
    // fused prep for this block's node range (float2 in -> half2 out)
    int base = blockIdx.x * 1024 * 32;          // element-pair index
    const float2* x2 = (const float2*)x;
    __half2* u02 = (__half2*)g_u0;
    #pragma unroll 4
    for (int t = threadIdx.x; t < 1024 * 32; t += 1024) {
        int idx = base + t;
        if (idx < NN * 32) {
            float di = g_dinv[idx >> 5];
            float2 v = __ldg(&x2[idx]);
            float2 o; o.x = di * v.x; o.y = di * v.y;
            u02[idx] = __float22half2_rn(o);
        }
    }
}

// 4) scatter edge sources into CSR buckets by dst — NO atomics
__global__ void k_scatter(const int* __restrict__ src, const int* __restrict__ dst) {
    int e = blockIdx.x * blockDim.x + threadIdx.x;
    if (e < NE) {
        int d = dst[e];
        int p = __ldg(&g_off[d]) + g_ppos[e];
        g_csr_src[p] = src[e];
    }
}

// ---- hop: warp per node, fp16 row-sum gather, fp32 accumulation ----
// PASS 0: in = g_u0 (fp16), out = g_u1 (fp16), scale = dinv^2
// PASS 1: in = g_u1 (fp16), out = g_h2 (fp16), scale = dinv
template <int PASS>
__global__ void k_hop() {
    const __half2* __restrict__ in2 =
        (PASS == 0) ? (const __half2*)g_u0 : (const __half2*)g_u1;

    int gw   = (blockIdx.x * blockDim.x + threadIdx.x) >> 5;
    int lane = threadIdx.x & 31;
    if (gw >= NN) return;
    const int i = gw;
    float2 acc = __half22float2(__ldg(&in2[i * 32 + lane]));   // self term
    int beg = g_off[i], end = g_off[i + 1];
    for (int c = beg; c < end; c += 32) {
        int n = end - c; if (n > 32) n = 32;
        int myS = (c + lane < end) ? __ldg(&g_csr_src[c + lane]) : 0;
        int k = 0;
        for (; k + 8 <= n; k += 8) {
            int s0 = __shfl_sync(0xffffffffu, myS, k + 0);
            int s1 = __shfl_sync(0xffffffffu, myS, k + 1);
            int s2 = __shfl_sync(0xffffffffu, myS, k + 2);
            int s3 = __shfl_sync(0xffffffffu, myS, k + 3);
            int s4 = __shfl_sync(0xffffffffu, myS, k + 4);
            int s5 = __shfl_sync(0xffffffffu, myS, k + 5);
            int s6 = __shfl_sync(0xffffffffu, myS, k + 6);
            int s7 = __shfl_sync(0xffffffffu, myS, k + 7);
            __half2 v0 = __ldg(&in2[s0 * 32 + lane]);
            __half2 v1 = __ldg(&in2[s1 * 32 + lane]);
            __half2 v2 = __ldg(&in2[s2 * 32 + lane]);
            __half2 v3 = __ldg(&in2[s3 * 32 + lane]);
            __half2 v4 = __ldg(&in2[s4 * 32 + lane]);
            __half2 v5 = __ldg(&in2[s5 * 32 + lane]);
            __half2 v6 = __ldg(&in2[s6 * 32 + lane]);
            __half2 v7 = __ldg(&in2[s7 * 32 + lane]);
            float2 f0 = __half22float2(v0), f1 = __half22float2(v1);
            float2 f2 = __half22float2(v2), f3 = __half22float2(v3);
            float2 f4 = __half22float2(v4), f5 = __half22float2(v5);
            float2 f6 = __half22float2(v6), f7 = __half22float2(v7);
            acc.x += f0.x; acc.y += f0.y;
            acc.x += f1.x; acc.y += f1.y;
            acc.x += f2.x; acc.y += f2.y;
            acc.x += f3.x; acc.y += f3.y;
            acc.x += f4.x; acc.y += f4.y;
            acc.x += f5.x; acc.y += f5.y;
            acc.x += f6.x; acc.y += f6.y;
            acc.x += f7.x; acc.y += f7.y;
        }
        for (; k + 2 <= n; k += 2) {
            int s0 = __shfl_sync(0xffffffffu, myS, k + 0);
            int s1 = __shfl_sync(0xffffffffu, myS, k + 1);
            float2 f0 = __half22float2(__ldg(&in2[s0 * 32 + lane]));
            float2 f1 = __half22float2(__ldg(&in2[s1 * 32 + lane]));
            acc.x += f0.x; acc.y += f0.y;
            acc.x += f1.x; acc.y += f1.y;
        }
        if (k < n) {
            int s = __shfl_sync(0xffffffffu, myS, k);
            float2 f = __half22float2(__ldg(&in2[s * 32 + lane]));
            acc.x += f.x; acc.y += f.y;
        }
    }
    float di = g_dinv[i];
    if (PASS == 0) {
        float sc = di * di;
        acc.x *= sc; acc.y *= sc;
        ((__half2*)g_u1)[i * 32 + lane] = __float22half2_rn(acc);
    } else {
        acc.x *= di; acc.y *= di;
        ((__half2*)g_h2)[i * 32 + lane] = __float22half2_rn(acc);
    }
}

// 5) out = g_h2 @ W^T + b  (packed fma.rn.f32x2: 2 cols x 4 rows per thread)
__global__ void k_lin(const float* __restrict__ W, const float* __restrict__ b,
                      float* __restrict__ out) {
    __shared__ unsigned long long Wp[D * 32];   // Wp[k*32+c2] = (W[2c2][k], W[2c2+1][k])
    __shared__ float hs[32 * D];                // 32 staged rows
    __shared__ unsigned long long bp[32];

    for (int t = threadIdx.x; t < D * 32; t += 256) {
        int k = t >> 5, c2 = t & 31;
        float lo = W[(2 * c2) * D + k];
        float hi = W[(2 * c2 + 1) * D + k];
        unsigned long long u;
        asm("mov.b64 %0, {%1, %2};" : "=l"(u) : "f"(lo), "f"(hi));
        Wp[t] = u;
    }
    if (threadIdx.x < 32) {
        unsigned long long u;
        asm("mov.b64 %0, {%1, %2};" : "=l"(u)
            : "f"(b[2 * threadIdx.x]), "f"(b[2 * threadIdx.x + 1]));
        bp[threadIdx.x] = u;
    }
    __syncthreads();

    int wid = threadIdx.x >> 5, lane = threadIdx.x & 31;

    for (int r0 = blockIdx.x * 32; r0 < NN; r0 += gridDim.x * 32) {
        const __half2* src = (const __half2*)g_h2 + r0 * 32;
        #pragma unroll
        for (int t = threadIdx.x; t < 1024; t += 256)
            ((float2*)hs)[t] = __half22float2(__ldg(&src[t]));
        __syncthreads();

        unsigned long long a0 = bp[lane], a1 = a0, a2 = a0, a3 = a0;
        const float* h0 = &hs[(wid * 4 + 0) * D];
        const float* h1 = &hs[(wid * 4 + 1) * D];
        const float* h2 = &hs[(wid * 4 + 2) * D];
        const float* h3 = &hs[(wid * 4 + 3) * D];
        #pragma unroll
        for (int k = 0; k < D; k++) {
            unsigned long long wv = Wp[k * 32 + lane];
            float v0 = h0[k], v1 = h1[k], v2 = h2[k], v3 = h3[k];
            unsigned long long p0, p1, p2, p3;
            asm("mov.b64 %0, {%1, %1};" : "=l"(p0) : "f"(v0));
            asm("mov.b64 %0, {%1, %1};" : "=l"(p1) : "f"(v1));
            asm("mov.b64 %0, {%1, %1};" : "=l"(p2) : "f"(v2));
            asm("mov.b64 %0, {%1, %1};" : "=l"(p3) : "f"(v3));
            asm("fma.rn.f32x2 %0, %1, %2, %3;" : "=l"(a0) : "l"(p0), "l"(wv), "l"(a0));
            asm("fma.rn.f32x2 %0, %1, %2, %3;" : "=l"(a1) : "l"(p1), "l"(wv), "l"(a1));
            asm("fma.rn.f32x2 %0, %1, %2, %3;" : "=l"(a2) : "l"(p2), "l"(wv), "l"(a2));
            asm("fma.rn.f32x2 %0, %1, %2, %3;" : "=l"(a3) : "l"(p3), "l"(wv), "l"(a3));
        }
        int r = r0 + wid * 4;
        unsigned long long* o = (unsigned long long*)out;
        o[(r + 0) * 32 + lane] = a0;
        o[(r + 1) * 32 + lane] = a1;
        o[(r + 2) * 32 + lane] = a2;
        o[(r + 3) * 32 + lane] = a3;
        __syncthreads();
    }
}

extern "C" void kernel_launch(void* const* d_in, const int* in_sizes, int n_in,
                              void* d_out, int out_size) {
    const float* x  = (const float*)d_in[0];                 // [NN, D]
    const int*   ei = (const int*)d_in[1];                   // [2, NE]
    const float* W  = (const float*)d_in[2];                 // [D, D]
    const float* b  = (const float*)d_in[3];                 // [D]
    const int* src = ei;
    const int* dst = ei + NE;
    float* out = (float*)d_out;

    void* deg_ptr = nullptr;
    cudaGetSymbolAddress(&deg_ptr, g_deg);
    cudaMemsetAsync(deg_ptr, 0, NN * sizeof(int));           // memset graph node

    k_hist<<<(NE + 255) / 256, 256>>>(dst);
    k_scan1<<<NB, 1024>>>();
    k_scan23<<<NB, 1024>>>(x);
    k_scatter<<<(NE + 255) / 256, 256>>>(src, dst);
    k_hop<0><<<(NN * 32 + 255) / 256, 256>>>();
    k_hop<1><<<(NN * 32 + 255) / 256, 256>>>();
    k_lin<<<1184, 256>>>(W, b, out);
}